// round 2
// baseline (speedup 1.0000x reference)
#include <cuda_runtime.h>
#include <mma.h>
#include <math.h>

using namespace nvcuda;

#define BSZ   64
#define TSZ   512
#define INSZ  1024
#define HIDSZ 1024
#define BH    65536                        // 64*1024
static constexpr size_t TBH = 33554432ull; // 512*64*1024

#define NCTA_REC 96                        // persistent grid (<=148 SMs -> co-resident)

// Scratch (device globals — no allocations allowed)
__device__ float g_gates[3ull * 512ull * 64ull * 1024ull]; // [gate][t*B + b][hid]
__device__ float g_hw[3 * BH];                             // per-step h@W_h per gate

// Grid barrier state (persist across replays; sense-reversal is start-value agnostic)
__device__ unsigned g_bar_cnt = 0;
__device__ volatile unsigned g_bar_gen = 0;

__device__ __forceinline__ void grid_barrier() {
    __syncthreads();
    if (threadIdx.x == 0) {
        __threadfence();
        unsigned gen = g_bar_gen;
        if (atomicAdd(&g_bar_cnt, 1u) == NCTA_REC - 1u) {
            g_bar_cnt = 0;
            __threadfence();
            g_bar_gen = gen + 1u;
        } else {
            while (g_bar_gen == gen) { }
            __threadfence();
        }
    }
    __syncthreads();
}

// ---------------------------------------------------------------------------
// Stage 1: gates[g][m][n] = sum_k x[m,k] * W_g[k,n]   (m = t*64 + b)
// x element for row m: inputs[(b*T + t)*IN + k]  (inputs is [B,T,IN])
// ---------------------------------------------------------------------------
__global__ void stage1_kernel(const float* __restrict__ x,
                              const float* __restrict__ Wr,
                              const float* __restrict__ Wz,
                              const float* __restrict__ Wn) {
    __shared__ __align__(32) float As[64][40];
    __shared__ __align__(32) float Bs[32][72];

    const int nb = blockIdx.x;          // 0..47 : gate*16 + ntile
    const int mb = blockIdx.y;          // 0..511
    const int gate = nb >> 4;
    const int col0 = (nb & 15) << 6;
    const float* W = (gate == 0) ? Wr : ((gate == 1) ? Wz : Wn);
    const int m0 = mb << 6;

    const int tid  = threadIdx.x;
    const int warp = tid >> 5;
    const int fr   = warp & 3;          // fragment row 0..3
    const int fc0  = (warp >> 2) << 1;  // fragment col pair base: 0 or 2

    wmma::fragment<wmma::accumulator, 16, 16, 8, float> acc[2];
    wmma::fill_fragment(acc[0], 0.0f);
    wmma::fill_fragment(acc[1], 0.0f);

    const int ar = tid >> 3;            // 0..31
    const int ac = (tid & 7) << 2;
    const int br = tid >> 4;            // 0..15
    const int bc = (tid & 15) << 2;

    for (int k0 = 0; k0 < INSZ; k0 += 32) {
#pragma unroll
        for (int rr = 0; rr < 2; rr++) {
            int m = m0 + ar + rr * 32;
            int t = m >> 6;
            int b = m & 63;
            float4 v = *(const float4*)(x + ((size_t)b * TSZ + t) * INSZ + k0 + ac);
            float* dst = &As[ar + rr * 32][ac];
            dst[0] = v.x; dst[1] = v.y; dst[2] = v.z; dst[3] = v.w;
        }
#pragma unroll
        for (int rr = 0; rr < 2; rr++) {
            float4 v = *(const float4*)(W + (size_t)(k0 + br + rr * 16) * HIDSZ + col0 + bc);
            float* dst = &Bs[br + rr * 16][bc];
            dst[0] = v.x; dst[1] = v.y; dst[2] = v.z; dst[3] = v.w;
        }
        __syncthreads();

#pragma unroll
        for (int kk = 0; kk < 4; kk++) {
            wmma::fragment<wmma::matrix_a, 16, 16, 8, wmma::precision::tf32, wmma::row_major> a;
            wmma::load_matrix_sync(a, &As[fr * 16][kk * 8], 40);
#pragma unroll
            for (int i = 0; i < a.num_elements; i++) a.x[i] = wmma::__float_to_tf32(a.x[i]);
#pragma unroll
            for (int j = 0; j < 2; j++) {
                wmma::fragment<wmma::matrix_b, 16, 16, 8, wmma::precision::tf32, wmma::row_major> bfr;
                wmma::load_matrix_sync(bfr, &Bs[kk * 8][(fc0 + j) * 16], 72);
#pragma unroll
                for (int i = 0; i < bfr.num_elements; i++) bfr.x[i] = wmma::__float_to_tf32(bfr.x[i]);
                wmma::mma_sync(acc[j], a, bfr, acc[j]);
            }
        }
        __syncthreads();
    }

#pragma unroll
    for (int j = 0; j < 2; j++) {
        float* p = g_gates + (size_t)gate * TBH
                 + (size_t)(m0 + fr * 16) * HIDSZ + col0 + (fc0 + j) * 16;
        wmma::store_matrix_sync(p, acc[j], HIDSZ, wmma::mem_row_major);
    }
}

// ---------------------------------------------------------------------------
// Persistent recurrence kernel. 96 CTAs x 128 threads.
// Per step t: phase A (gemm hW = h_{t-1} @ W_h, gate-split across CTAs),
// barrier, phase B (pointwise -> h_t into out), barrier.
// ---------------------------------------------------------------------------
__global__ __launch_bounds__(128, 1)
void recur_kernel(const float* __restrict__ Wr,
                  const float* __restrict__ Wz,
                  const float* __restrict__ Wn,
                  const float* __restrict__ b_ir, const float* __restrict__ b_hr,
                  const float* __restrict__ b_iz, const float* __restrict__ b_hz,
                  const float* __restrict__ b_in, const float* __restrict__ b_hn,
                  float* __restrict__ out, int write_hfinal) {
    __shared__ __align__(32) float As[64][72];   // h tile 64x64 (+pad)
    __shared__ __align__(32) float Bs[64][36];   // W tile 64x32 (+pad)

    const int cta  = blockIdx.x;
    const int tid  = threadIdx.x;
    const int warp = tid >> 5;                   // 0..3
    const int wm   = warp & 1;                   // row half (32 rows)
    const int wn   = warp >> 1;                  // col half (16 cols)

    const int g    = cta >> 5;                   // gate 0..2
    const int col0 = (cta & 31) << 5;            // 32-col tile
    const float* W = (g == 0) ? Wr : ((g == 1) ? Wz : Wn);

    // Phase B per-thread fixed column -> biases in registers
    const int i0 = cta * 128 + tid;              // stride NCTA_REC*128 = 12288 = 12*1024
    const int jj = i0 & 1023;
    const float vb_ir = b_ir[jj], vb_hr = b_hr[jj];
    const float vb_iz = b_iz[jj], vb_hz = b_hz[jj];
    const float vb_in = b_in[jj], vb_hn = b_hn[jj];

    for (int t = 0; t < TSZ; t++) {
        if (t > 0) {
            // ---------------- Phase A: hW tile [64 x 32] for gate g ----------
            const float* h = out + (size_t)(t - 1) * BH;

            wmma::fragment<wmma::accumulator, 16, 16, 8, float> acc0, acc1;
            wmma::fill_fragment(acc0, 0.0f);
            wmma::fill_fragment(acc1, 0.0f);

            for (int k0 = 0; k0 < HIDSZ; k0 += 64) {
                // h tile [64 x 64]
#pragma unroll
                for (int q = 0; q < 8; q++) {
                    int idx = tid + q * 128;         // 0..1023
                    int r  = idx >> 4;
                    int c4 = (idx & 15) << 2;
                    float4 v = *(const float4*)(h + (size_t)r * HIDSZ + k0 + c4);
                    float* dst = &As[r][c4];
                    dst[0] = v.x; dst[1] = v.y; dst[2] = v.z; dst[3] = v.w;
                }
                // W tile [64 x 32]
#pragma unroll
                for (int q = 0; q < 4; q++) {
                    int idx = tid + q * 128;         // 0..511
                    int r  = idx >> 3;
                    int c4 = (idx & 7) << 2;
                    float4 v = *(const float4*)(W + (size_t)(k0 + r) * HIDSZ + col0 + c4);
                    float* dst = &Bs[r][c4];
                    dst[0] = v.x; dst[1] = v.y; dst[2] = v.z; dst[3] = v.w;
                }
                __syncthreads();

#pragma unroll
                for (int kk = 0; kk < 8; kk++) {
                    wmma::fragment<wmma::matrix_b, 16, 16, 8, wmma::precision::tf32, wmma::row_major> bfr;
                    wmma::load_matrix_sync(bfr, &Bs[kk * 8][wn * 16], 36);
#pragma unroll
                    for (int i = 0; i < bfr.num_elements; i++) bfr.x[i] = wmma::__float_to_tf32(bfr.x[i]);

                    wmma::fragment<wmma::matrix_a, 16, 16, 8, wmma::precision::tf32, wmma::row_major> a0, a1;
                    wmma::load_matrix_sync(a0, &As[wm * 32][kk * 8], 72);
                    wmma::load_matrix_sync(a1, &As[wm * 32 + 16][kk * 8], 72);
#pragma unroll
                    for (int i = 0; i < a0.num_elements; i++) a0.x[i] = wmma::__float_to_tf32(a0.x[i]);
#pragma unroll
                    for (int i = 0; i < a1.num_elements; i++) a1.x[i] = wmma::__float_to_tf32(a1.x[i]);

                    wmma::mma_sync(acc0, a0, bfr, acc0);
                    wmma::mma_sync(acc1, a1, bfr, acc1);
                }
                __syncthreads();
            }

            // store hW tile
            float* pw = g_hw + (size_t)g * BH + (size_t)col0 + wn * 16;
            wmma::store_matrix_sync(pw + (size_t)(wm * 32) * HIDSZ,      acc0, HIDSZ, wmma::mem_row_major);
            wmma::store_matrix_sync(pw + (size_t)(wm * 32 + 16) * HIDSZ, acc1, HIDSZ, wmma::mem_row_major);

            grid_barrier();
        }

        // ---------------- Phase B: pointwise GRU update ----------------------
        {
            const size_t toff = (size_t)t * BH;
            const float* hprev = out + (size_t)(t - 1) * BH;  // unused at t==0
            float* hout = out + toff;

            for (int i = i0; i < BH; i += NCTA_REC * 128) {
                float gr = g_gates[toff + i]              + vb_ir;
                float gz = g_gates[TBH + toff + i]        + vb_iz;
                float gn = g_gates[2ull * TBH + toff + i] + vb_in;

                float hr = vb_hr, hz = vb_hz, hn = vb_hn, hp = 0.0f;
                if (t > 0) {
                    hr += g_hw[i];
                    hz += g_hw[BH + i];
                    hn += g_hw[2 * BH + i];
                    hp  = hprev[i];
                }

                float r = 1.0f / (1.0f + expf(-(gr + hr)));
                float z = 1.0f / (1.0f + expf(-(gz + hz)));
                float n = tanhf(gn + r * hn);
                float hnew = (1.0f - z) * n + z * hp;

                hout[i] = hnew;
                if (t == TSZ - 1 && write_hfinal) out[TBH + i] = hnew;
            }
        }
        grid_barrier();
    }
}

// ---------------------------------------------------------------------------
extern "C" void kernel_launch(void* const* d_in, const int* in_sizes, int n_in,
                              void* d_out, int out_size) {
    const float* x    = (const float*)d_in[0];
    const float* W_ir = (const float*)d_in[1];
    const float* b_ir = (const float*)d_in[2];
    const float* W_hr = (const float*)d_in[3];
    const float* b_hr = (const float*)d_in[4];
    const float* W_iz = (const float*)d_in[5];
    const float* b_iz = (const float*)d_in[6];
    const float* W_hz = (const float*)d_in[7];
    const float* b_hz = (const float*)d_in[8];
    const float* W_in = (const float*)d_in[9];
    const float* b_in = (const float*)d_in[10];
    const float* W_hn = (const float*)d_in[11];
    const float* b_hn = (const float*)d_in[12];
    float* out = (float*)d_out;

    const int has_hfinal = ((size_t)out_size >= TBH + (size_t)BH) ? 1 : 0;

    // Node 1: all input-side projections
    stage1_kernel<<<dim3(48, 512), 256>>>(x, W_ir, W_iz, W_in);

    // Node 2: entire recurrence in one persistent kernel (grid-barrier synced)
    recur_kernel<<<NCTA_REC, 128>>>(W_hr, W_hz, W_hn,
                                    b_ir, b_hr, b_iz, b_hz, b_in, b_hn,
                                    out, has_hfinal);
}

// round 3
// speedup vs baseline: 1.3378x; 1.3378x over previous
#include <cuda_runtime.h>
#include <mma.h>
#include <math.h>

using namespace nvcuda;

#define BSZ   64
#define TSZ   512
#define INSZ  1024
#define HIDSZ 1024
#define BH    65536                        // 64*1024
static constexpr size_t TBH = 33554432ull; // 512*64*1024

#define NCTA_REC 96                        // persistent grid, 1 CTA/SM

// Scratch (device globals — no allocations allowed)
__device__ float g_gates[3ull * 512ull * 64ull * 1024ull]; // [gate][t*B+b][hid]
__device__ float g_hw[3 * BH];                             // per-step h@W_h per gate

// Grid barrier state
__device__ unsigned g_bar_cnt = 0;
__device__ unsigned g_bar_gen = 0;

__device__ __forceinline__ unsigned ld_acquire_gpu(const unsigned* p) {
    unsigned v;
    asm volatile("ld.acquire.gpu.u32 %0, [%1];" : "=r"(v) : "l"(p) : "memory");
    return v;
}
__device__ __forceinline__ void st_release_gpu(unsigned* p, unsigned v) {
    asm volatile("st.release.gpu.u32 [%0], %1;" :: "l"(p), "r"(v) : "memory");
}

// Sense-free barrier: caller supplies the absolute target generation.
__device__ __forceinline__ void grid_barrier(unsigned target_gen) {
    __syncthreads();
    if (threadIdx.x == 0) {
        __threadfence();   // release my writes (emits gpu-scope fence -> L1 inval)
        unsigned old = atomicAdd(&g_bar_cnt, 1u);
        if (old == NCTA_REC - 1u) {
            g_bar_cnt = 0u;                       // ordered before release below
            st_release_gpu(&g_bar_gen, target_gen);
        } else {
            while (ld_acquire_gpu(&g_bar_gen) != target_gen) __nanosleep(64);
        }
        __threadfence();   // acquire side: invalidate L1 so ALL warps see remote writes
    }
    __syncthreads();
}

// ---------------------------------------------------------------------------
// Stage 1: gates[g][m][n] = sum_k x[m,k] * W_g[k,n]   (m = t*64 + b)
// x element for row m: inputs[(b*T + t)*IN + k]  (inputs is [B,T,IN])
// tf32 conversion hoisted into the smem stores.
// ---------------------------------------------------------------------------
__global__ void stage1_kernel(const float* __restrict__ x,
                              const float* __restrict__ Wr,
                              const float* __restrict__ Wz,
                              const float* __restrict__ Wn) {
    __shared__ __align__(32) float As[64][40];
    __shared__ __align__(32) float Bs[32][72];

    const int nb = blockIdx.x;          // 0..47 : gate*16 + ntile
    const int mb = blockIdx.y;          // 0..511
    const int gate = nb >> 4;
    const int col0 = (nb & 15) << 6;
    const float* W = (gate == 0) ? Wr : ((gate == 1) ? Wz : Wn);
    const int m0 = mb << 6;

    const int tid  = threadIdx.x;
    const int warp = tid >> 5;
    const int fr   = warp & 3;
    const int fc0  = (warp >> 2) << 1;

    wmma::fragment<wmma::accumulator, 16, 16, 8, float> acc[2];
    wmma::fill_fragment(acc[0], 0.0f);
    wmma::fill_fragment(acc[1], 0.0f);

    const int ar = tid >> 3;
    const int ac = (tid & 7) << 2;
    const int br = tid >> 4;
    const int bc = (tid & 15) << 2;

    for (int k0 = 0; k0 < INSZ; k0 += 32) {
#pragma unroll
        for (int rr = 0; rr < 2; rr++) {
            int m = m0 + ar + rr * 32;
            int t = m >> 6;
            int b = m & 63;
            float4 v = *(const float4*)(x + ((size_t)b * TSZ + t) * INSZ + k0 + ac);
            float* dst = &As[ar + rr * 32][ac];
            dst[0] = wmma::__float_to_tf32(v.x); dst[1] = wmma::__float_to_tf32(v.y);
            dst[2] = wmma::__float_to_tf32(v.z); dst[3] = wmma::__float_to_tf32(v.w);
        }
#pragma unroll
        for (int rr = 0; rr < 2; rr++) {
            float4 v = *(const float4*)(W + (size_t)(k0 + br + rr * 16) * HIDSZ + col0 + bc);
            float* dst = &Bs[br + rr * 16][bc];
            dst[0] = wmma::__float_to_tf32(v.x); dst[1] = wmma::__float_to_tf32(v.y);
            dst[2] = wmma::__float_to_tf32(v.z); dst[3] = wmma::__float_to_tf32(v.w);
        }
        __syncthreads();

#pragma unroll
        for (int kk = 0; kk < 4; kk++) {
            wmma::fragment<wmma::matrix_a, 16, 16, 8, wmma::precision::tf32, wmma::row_major> a;
            wmma::load_matrix_sync(a, &As[fr * 16][kk * 8], 40);
#pragma unroll
            for (int j = 0; j < 2; j++) {
                wmma::fragment<wmma::matrix_b, 16, 16, 8, wmma::precision::tf32, wmma::row_major> bfr;
                wmma::load_matrix_sync(bfr, &Bs[kk * 8][(fc0 + j) * 16], 72);
                wmma::mma_sync(acc[j], a, bfr, acc[j]);
            }
        }
        __syncthreads();
    }

#pragma unroll
    for (int j = 0; j < 2; j++) {
        float* p = g_gates + (size_t)gate * TBH
                 + (size_t)(m0 + fr * 16) * HIDSZ + col0 + (fc0 + j) * 16;
        wmma::store_matrix_sync(p, acc[j], HIDSZ, wmma::mem_row_major);
    }
}

// ---------------------------------------------------------------------------
// Persistent recurrence. 96 CTAs x 256 threads, dynamic smem:
//   Ws[1024][36]  resident W slice (tf32, loaded once)        147456 B
//   hb[8][64][36] h tiles: 2 pipeline stages x 4 K-groups       73728 B
// Phase A: hW = h_{t-1} @ W (gate-split + 4-way K-split, 32x32 warp tiles)
// Phase B: pointwise GRU update -> out
// ---------------------------------------------------------------------------
#define SMEM_WS_FLOATS  (1024 * 36)
#define SMEM_REC_BYTES  (147456 + 73728)

__global__ __launch_bounds__(256, 1)
void recur_kernel(const float* __restrict__ Wr,
                  const float* __restrict__ Wz,
                  const float* __restrict__ Wn,
                  const float* __restrict__ b_ir, const float* __restrict__ b_hr,
                  const float* __restrict__ b_iz, const float* __restrict__ b_hz,
                  const float* __restrict__ b_in, const float* __restrict__ b_hn,
                  float* __restrict__ out, int write_hfinal) {
    extern __shared__ __align__(16) char smem[];
    float (*Ws)[36] = (float(*)[36])smem;                       // [1024][36]
    float (*hb)[64][36] = (float(*)[64][36])(smem + 147456);    // [8][64][36]
    float* red = (float*)(smem + 147456);                        // reduce scratch (reuse)

    const int cta  = blockIdx.x;
    const int tid  = threadIdx.x;
    const int warp = tid >> 5;
    const int grp  = warp >> 1;                  // K-group 0..3 (k in [grp*256, +256))
    const int wr   = warp & 1;                   // row half (32 batch rows)

    const int gate = cta >> 5;                   // 0..2
    const int col0 = (cta & 31) << 5;            // 32-col tile
    const float* W = (gate == 0) ? Wr : ((gate == 1) ? Wz : Wn);

    // Barrier generation base (replay-safe: read before any barrier can fire)
    __shared__ unsigned s_gen0;
    if (tid == 0) s_gen0 = *(volatile unsigned*)&g_bar_gen;

    // Load resident W slice (1024 x 32), tf32-rounded. 128 floats/thread.
    for (int q = 0; q < 32; q++) {
        int idx = tid + q * 256;                 // 0..8191 float4s
        int k   = idx >> 3;
        int c4  = (idx & 7) << 2;
        float4 v = *(const float4*)(W + (size_t)k * HIDSZ + col0 + c4);
        float* dst = &Ws[k][c4];
        dst[0] = wmma::__float_to_tf32(v.x); dst[1] = wmma::__float_to_tf32(v.y);
        dst[2] = wmma::__float_to_tf32(v.z); dst[3] = wmma::__float_to_tf32(v.w);
    }
    __syncthreads();
    unsigned gen = s_gen0;

    // Phase-B per-thread fixed column -> biases in registers
    const int i0 = cta * 256 + tid;              // stride 24576 = 24*1024
    const int jj = i0 & 1023;
    const float vb_ir = b_ir[jj], vb_hr = b_hr[jj];
    const float vb_iz = b_iz[jj], vb_hz = b_hz[jj];
    const float vb_in = b_in[jj], vb_hn = b_hn[jj];

    for (int t = 0; t < TSZ; t++) {
        if (t > 0) {
            // ============ Phase A: hW tile [64 x 32] for this gate ============
            const float* h = out + (size_t)(t - 1) * BH;

            wmma::fragment<wmma::accumulator, 16, 16, 8, float> acc[2][2];
#pragma unroll
            for (int mi = 0; mi < 2; mi++)
#pragma unroll
                for (int ni = 0; ni < 2; ni++) wmma::fill_fragment(acc[mi][ni], 0.0f);

            // Preload iteration 0: 4 tiles (one per K-group), each [64 x 32k]
            {
#pragma unroll
                for (int q = 0; q < 8; q++) {
                    int gidx = tid + q * 256;        // 0..2047 float4s
                    int tg   = gidx >> 9;            // group 0..3
                    int idx  = gidx & 511;
                    int row  = idx >> 3;
                    int c4   = (idx & 7) << 2;
                    float4 v = *(const float4*)(h + (size_t)row * HIDSZ + tg * 256 + c4);
                    float* dst = &hb[tg][row][c4];
                    dst[0] = wmma::__float_to_tf32(v.x); dst[1] = wmma::__float_to_tf32(v.y);
                    dst[2] = wmma::__float_to_tf32(v.z); dst[3] = wmma::__float_to_tf32(v.w);
                }
            }
            __syncthreads();

            for (int it = 0; it < 8; it++) {
                // stage loads for it+1 into registers (latency overlapped w/ compute)
                float4 st[8];
                if (it < 7) {
#pragma unroll
                    for (int q = 0; q < 8; q++) {
                        int gidx = tid + q * 256;
                        int tg   = gidx >> 9;
                        int idx  = gidx & 511;
                        int row  = idx >> 3;
                        int c4   = (idx & 7) << 2;
                        st[q] = *(const float4*)(h + (size_t)row * HIDSZ
                                                 + tg * 256 + (it + 1) * 32 + c4);
                    }
                }

                // compute current buffer
                {
                    const float (*A)[36] = hb[(it & 1) * 4 + grp];
                    const int kbase = grp * 256 + it * 32;
#pragma unroll
                    for (int kk = 0; kk < 4; kk++) {
                        wmma::fragment<wmma::matrix_a, 16, 16, 8, wmma::precision::tf32, wmma::row_major> a0, a1;
                        wmma::load_matrix_sync(a0, &A[wr * 32][kk * 8], 36);
                        wmma::load_matrix_sync(a1, &A[wr * 32 + 16][kk * 8], 36);
                        wmma::fragment<wmma::matrix_b, 16, 16, 8, wmma::precision::tf32, wmma::row_major> b0, b1;
                        wmma::load_matrix_sync(b0, &Ws[kbase + kk * 8][0],  36);
                        wmma::load_matrix_sync(b1, &Ws[kbase + kk * 8][16], 36);
                        wmma::mma_sync(acc[0][0], a0, b0, acc[0][0]);
                        wmma::mma_sync(acc[0][1], a0, b1, acc[0][1]);
                        wmma::mma_sync(acc[1][0], a1, b0, acc[1][0]);
                        wmma::mma_sync(acc[1][1], a1, b1, acc[1][1]);
                    }
                }

                if (it < 7) {
#pragma unroll
                    for (int q = 0; q < 8; q++) {
                        int gidx = tid + q * 256;
                        int tg   = gidx >> 9;
                        int idx  = gidx & 511;
                        int row  = idx >> 3;
                        int c4   = (idx & 7) << 2;
                        float* dst = &hb[((it + 1) & 1) * 4 + tg][row][c4];
                        dst[0] = wmma::__float_to_tf32(st[q].x);
                        dst[1] = wmma::__float_to_tf32(st[q].y);
                        dst[2] = wmma::__float_to_tf32(st[q].z);
                        dst[3] = wmma::__float_to_tf32(st[q].w);
                    }
                }
                __syncthreads();
            }

            // K-split reduction: groups 1..3 publish partials, group 0 sums.
            if (grp > 0) {
                float* s = red + (size_t)((grp - 1) * 2 + wr) * 1024;   // 32x32 region
#pragma unroll
                for (int mi = 0; mi < 2; mi++)
#pragma unroll
                    for (int ni = 0; ni < 2; ni++)
                        wmma::store_matrix_sync(s + mi * 16 * 32 + ni * 16,
                                                acc[mi][ni], 32, wmma::mem_row_major);
            }
            __syncthreads();
            if (grp == 0) {
#pragma unroll
                for (int src = 0; src < 3; src++) {
                    const float* s = red + (size_t)(src * 2 + wr) * 1024;
#pragma unroll
                    for (int mi = 0; mi < 2; mi++)
#pragma unroll
                        for (int ni = 0; ni < 2; ni++) {
                            wmma::fragment<wmma::accumulator, 16, 16, 8, float> p;
                            wmma::load_matrix_sync(p, s + mi * 16 * 32 + ni * 16, 32,
                                                   wmma::mem_row_major);
#pragma unroll
                            for (int e = 0; e < p.num_elements; e++)
                                acc[mi][ni].x[e] += p.x[e];
                        }
                }
                float* pw = g_hw + (size_t)gate * BH + col0;
#pragma unroll
                for (int mi = 0; mi < 2; mi++)
#pragma unroll
                    for (int ni = 0; ni < 2; ni++)
                        wmma::store_matrix_sync(pw + (size_t)(wr * 32 + mi * 16) * HIDSZ + ni * 16,
                                                acc[mi][ni], HIDSZ, wmma::mem_row_major);
            }
            gen++; grid_barrier(gen);
        }

        // ============ Phase B: pointwise GRU update ============
        {
            const size_t toff = (size_t)t * BH;
            const float* hprev = out + (size_t)(t - 1) * BH;
            float* hout = out + toff;

            for (int i = i0; i < BH; i += NCTA_REC * 256) {
                float gr = g_gates[toff + i]              + vb_ir;
                float gz = g_gates[TBH + toff + i]        + vb_iz;
                float gn = g_gates[2ull * TBH + toff + i] + vb_in;

                float hr = vb_hr, hz = vb_hz, hn = vb_hn, hp = 0.0f;
                if (t > 0) {
                    hr += g_hw[i];
                    hz += g_hw[BH + i];
                    hn += g_hw[2 * BH + i];
                    hp  = hprev[i];
                }

                float r = 1.0f / (1.0f + expf(-(gr + hr)));
                float z = 1.0f / (1.0f + expf(-(gz + hz)));
                float n = tanhf(gn + r * hn);
                float hnew = (1.0f - z) * n + z * hp;

                hout[i] = hnew;
                if (t == TSZ - 1 && write_hfinal) out[TBH + i] = hnew;
            }
        }
        gen++; grid_barrier(gen);
    }
}

// ---------------------------------------------------------------------------
extern "C" void kernel_launch(void* const* d_in, const int* in_sizes, int n_in,
                              void* d_out, int out_size) {
    const float* x    = (const float*)d_in[0];
    const float* W_ir = (const float*)d_in[1];
    const float* b_ir = (const float*)d_in[2];
    const float* W_hr = (const float*)d_in[3];
    const float* b_hr = (const float*)d_in[4];
    const float* W_iz = (const float*)d_in[5];
    const float* b_iz = (const float*)d_in[6];
    const float* W_hz = (const float*)d_in[7];
    const float* b_hz = (const float*)d_in[8];
    const float* W_in = (const float*)d_in[9];
    const float* b_in = (const float*)d_in[10];
    const float* W_hn = (const float*)d_in[11];
    const float* b_hn = (const float*)d_in[12];
    float* out = (float*)d_out;

    const int has_hfinal = ((size_t)out_size >= TBH + (size_t)BH) ? 1 : 0;

    static int attr_done = 0;
    if (!attr_done) {
        cudaFuncSetAttribute(recur_kernel,
                             cudaFuncAttributeMaxDynamicSharedMemorySize,
                             SMEM_REC_BYTES);
        attr_done = 1;
    }

    stage1_kernel<<<dim3(48, 512), 256>>>(x, W_ir, W_iz, W_in);

    recur_kernel<<<NCTA_REC, 256, SMEM_REC_BYTES>>>(
        W_hr, W_hz, W_hn,
        b_ir, b_hr, b_iz, b_hz, b_in, b_hn,
        out, has_hfinal);
}